// round 3
// baseline (speedup 1.0000x reference)
#include <cuda_runtime.h>
#include <stdint.h>

#define BB    32
#define NBOX  8192
#define MGT   256
#define NP    8448        // NBOX + MGT
#define SORTN 16384
#define NSAMP 512
#define NFG   128

// scratch (device globals -- no allocation allowed)
__device__ unsigned long long g_keys[BB * NP];
__device__ unsigned int       g_meta[BB * NP];

__device__ __forceinline__ uint32_t rotl32(uint32_t x, int d) {
    return (x << d) | (x >> (32 - d));
}

// JAX *partitionable* threefry (default in modern jax), key = (0, 42).
// bits(p) = x0 ^ x1 of threefry2x32((0,42), (0, p))
__device__ __forceinline__ uint32_t threefry_bits(uint32_t p) {
    const uint32_t ks0 = 0u, ks1 = 42u, ks2 = 0x1BD11BF0u;  // 0x1BD11BDA ^ 0 ^ 42
    uint32_t x0 = 0u + ks0;        // counts_hi = 0
    uint32_t x1 = p + ks1;         // counts_lo = p
#define TF_R(r) { x0 += x1; x1 = rotl32(x1, (r)); x1 ^= x0; }
    TF_R(13) TF_R(15) TF_R(26) TF_R(6)   x0 += ks1; x1 += ks2 + 1u;
    TF_R(17) TF_R(29) TF_R(16) TF_R(24)  x0 += ks2; x1 += ks0 + 2u;
    TF_R(13) TF_R(15) TF_R(26) TF_R(6)   x0 += ks0; x1 += ks1 + 3u;
    TF_R(17) TF_R(29) TF_R(16) TF_R(24)  x0 += ks1; x1 += ks2 + 4u;
    TF_R(13) TF_R(15) TF_R(26) TF_R(6)   x0 += ks2; x1 += ks0 + 5u;
#undef TF_R
    return x0 ^ x1;
}

// ---------------------------------------------------------------------------
// Kernel 1: per-box max-IoU matching + classification + threefry sort key.
// ---------------------------------------------------------------------------
__global__ __launch_bounds__(256)
void roi_match_kernel(const float* __restrict__ boxes,
                      const float* __restrict__ gt_boxes) {
    __shared__ float4 sg[MGT];
    __shared__ float  sga[MGT];

    const int b = blockIdx.y;
    {
        const int j = threadIdx.x;               // 256 threads == MGT
        float4 g = ((const float4*)gt_boxes)[b * MGT + j];
        float mx = fmaxf(fmaxf(g.x, g.y), fmaxf(g.z, g.w));
        float area = (g.z - g.x) * (g.w - g.y);
        if (mx < 0.0f) {                         // invalid gt -> force rejection
            g.x = 1e30f; g.y = 1e30f; g.z = -1e30f; g.w = -1e30f;
            area = 0.0f;
        }
        sg[j] = g; sga[j] = area;
    }
    __syncthreads();

    const int i = blockIdx.x * 256 + threadIdx.x;   // grid exact: i < NP
    float4 bx = (i < NBOX) ? ((const float4*)boxes)[b * NBOX + i]
                           : ((const float4*)gt_boxes)[b * MGT + (i - NBOX)];
    const float ab = (bx.z - bx.x) * (bx.w - bx.y);

    float bi = -1.0f, bu = 1.0f;   // best (inter, union)
    int mi = 0;
#pragma unroll 4
    for (int g = 0; g < MGT; ++g) {
        float4 gb = sg[g];
        float dy = fminf(bx.z, gb.z) - fmaxf(bx.x, gb.x);
        float dx = fminf(bx.w, gb.w) - fmaxf(bx.y, gb.y);
        if (dy > 0.0f && dx > 0.0f) {
            float inter = dy * dx;
            float uni   = (ab + sga[g]) - inter;
            // inter/uni > bi/bu  <=>  inter*bu > bi*uni   (uni, bu > 0)
            if (inter * bu > bi * uni) { bi = inter; bu = uni; mi = g; }
        }
    }
    bool pos = (bi > 0.0f) && (__fdiv_rn(bi, bu) >= 0.5f);

    uint32_t p = (uint32_t)(b * NP + i);
    uint32_t m = threefry_bits(p) >> 9;       // 23-bit mantissa; order(r) == order(m)
    g_keys[b * NP + i] =
        (((unsigned long long)(0x7FFFFFu - m)) << 14) | (unsigned)i;  // asc == r desc, idx asc
    g_meta[b * NP + i] = (unsigned)mi | (pos ? (1u << 16) : 0u);
}

// ---------------------------------------------------------------------------
// Kernel 2: per-image sort + rank + select + final-order + gather.
// ---------------------------------------------------------------------------
__device__ __forceinline__ void write_record(
    const float* __restrict__ boxes, const float* __restrict__ gt_boxes,
    const int* __restrict__ gt_classes, const unsigned int* meta,
    float* __restrict__ out, int b, unsigned i, unsigned slot)
{
    float4 roi = (i < NBOX)
        ? ((const float4*)boxes)[b * NBOX + i]
        : ((const float4*)gt_boxes)[b * MGT + (i - NBOX)];
    unsigned mt = meta[i];
    bool pos = (mt >> 16) & 1u;
    int  mi  = (int)(mt & 0xFFFFu);
    float4 gb = make_float4(0.f, 0.f, 0.f, 0.f);
    float cls = 0.0f, gidx = -1.0f;
    if (pos) {
        gb   = ((const float4*)gt_boxes)[b * MGT + mi];
        cls  = (float)gt_classes[b * MGT + mi];
        gidx = (float)mi;
    }
    size_t base = (size_t)(b * NSAMP + slot);
    float* o1 = out + base * 4;                                   // rois
    o1[0] = roi.x; o1[1] = roi.y; o1[2] = roi.z; o1[3] = roi.w;
    float* o2 = out + (size_t)BB * NSAMP * 4 + base * 4;          // matched gt boxes
    o2[0] = gb.x; o2[1] = gb.y; o2[2] = gb.z; o2[3] = gb.w;
    out[(size_t)2 * BB * NSAMP * 4 + base] = cls;                 // classes
    out[(size_t)2 * BB * NSAMP * 4 + (size_t)BB * NSAMP + base] = gidx; // indices
}

__global__ __launch_bounds__(1024)
void roi_sample_kernel(const float* __restrict__ boxes,
                       const float* __restrict__ gt_boxes,
                       const int*   __restrict__ gt_classes,
                       float* __restrict__ out) {
    extern __shared__ unsigned char smem_raw[];
    unsigned long long* sk   = (unsigned long long*)smem_raw;   // SORTN keys
    unsigned int*       meta = (unsigned int*)(sk + SORTN);     // NP metas
    unsigned int*       scan = meta + NP;                       // 1024 scan
    unsigned long long* selk = (unsigned long long*)(scan + 1024); // NSAMP sel keys

    const int b = blockIdx.x;
    const int t = threadIdx.x;
    const int T = 1024;

    for (int p = t; p < SORTN; p += T)
        sk[p] = (p < NP) ? g_keys[b * NP + p] : ~0ull;
    for (int p = t; p < NP; p += T)
        meta[p] = g_meta[b * NP + p];
    __syncthreads();

    // bitonic sort ascending (position 0 = largest r, ties by smaller idx)
    for (unsigned k = 2; k <= SORTN; k <<= 1) {
        for (unsigned j = k >> 1; j > 0; j >>= 1) {
            for (unsigned p = t; p < SORTN; p += T) {
                unsigned q = p ^ j;
                if (q > p) {
                    unsigned long long a = sk[p], c = sk[q];
                    bool up = ((p & k) == 0);
                    if ((a > c) == up) { sk[p] = c; sk[q] = a; }
                }
            }
            __syncthreads();
        }
    }

    const int lo = t * 9;
    const int hi = (lo + 9 < NP) ? (lo + 9) : NP;

    // ---- pass A: count positives per chunk, block scan -> pos ranks ----
    unsigned cpos = 0;
    for (int p = lo; p < hi; ++p) {
        unsigned i = (unsigned)(sk[p] & 0x3FFFu);
        cpos += (meta[i] >> 16) & 1u;
    }
    scan[t] = cpos;
    __syncthreads();
    for (int off = 1; off < T; off <<= 1) {
        unsigned v = (t >= off) ? scan[t - off] : 0u;
        __syncthreads();
        scan[t] += v;
        __syncthreads();
    }
    unsigned excl_pos  = scan[t] - cpos;
    unsigned total_pos = scan[T - 1];
    unsigned n_pos = (total_pos < (unsigned)NFG) ? total_pos : (unsigned)NFG;
    unsigned quota = (unsigned)NSAMP - n_pos;
    __syncthreads();

    // ---- pass B: selection mask (pos_rank<128 | neg_rank<quota), scan ----
    unsigned run = excl_pos, selc = 0;
    for (int p = lo; p < hi; ++p) {
        unsigned long long k = sk[p];
        unsigned i  = (unsigned)(k & 0x3FFFu);
        unsigned ps = (meta[i] >> 16) & 1u;
        bool sel = ps ? (run < (unsigned)NFG) : (((unsigned)p - run) < quota);
        run += ps;
        if (sel) { sk[p] = k | (1ull << 62); selc++; }
    }
    scan[t] = selc;
    __syncthreads();
    for (int off = 1; off < T; off <<= 1) {
        unsigned v = (t >= off) ? scan[t - off] : 0u;
        __syncthreads();
        scan[t] += v;
        __syncthreads();
    }
    unsigned excl_sel  = scan[t] - selc;
    unsigned total_sel = scan[T - 1];
    if (t < NSAMP) selk[t] = ~0ull;   // T == 1024 >= NSAMP... (guard: per-thread once)
    for (int s = t; s < NSAMP; s += T) selk[s] = ~0ull;
    __syncthreads();

    // ---- pass C: selected -> rounded-score keys; unselected fill direct ----
    // Final output order is top_k(selected*2.0f + r). For selected items the
    // float add 2.0f + r rounds r's 23-bit mantissa m to the 2^-22 grid (RNE):
    //   h = (m>>1) + ((m&1) & ((m>>1)&1))
    // creating ties broken by index. Unselected scores (= r) are exact.
    unsigned runs = excl_sel;
    for (int p = lo; p < hi; ++p) {
        unsigned long long k = sk[p];
        bool sel = (k >> 62) & 1ull;
        unsigned i = (unsigned)(k & 0x3FFFu);
        if (sel) {
            unsigned mm = 0x7FFFFFu - (unsigned)((k >> 14) & 0x7FFFFFu);
            unsigned h  = (mm >> 1) + ((mm & 1u) & ((mm >> 1) & 1u));
            selk[runs] = (((unsigned long long)(0x7FFFFFu - h)) << 14) | i;
            runs++;
        } else {
            unsigned slot = total_sel + ((unsigned)p - runs);
            if (slot < (unsigned)NSAMP)   // only if total_sel < 512 (never in practice)
                write_record(boxes, gt_boxes, gt_classes, meta, out, b, i, slot);
        }
    }
    __syncthreads();

    // ---- sort the <=512 selected keys (score desc, idx asc == key asc) ----
    for (unsigned k = 2; k <= (unsigned)NSAMP; k <<= 1) {
        for (unsigned j = k >> 1; j > 0; j >>= 1) {
            if (t < NSAMP) {
                unsigned p = (unsigned)t, q = p ^ j;
                if (q > p) {
                    unsigned long long a = selk[p], c = selk[q];
                    bool up = ((p & k) == 0);
                    if ((a > c) == up) { selk[p] = c; selk[q] = a; }
                }
            }
            __syncthreads();
        }
    }

    // ---- gather selected outputs ----
    for (int s = t; s < NSAMP; s += T) {
        if ((unsigned)s < total_sel) {
            unsigned i = (unsigned)(selk[s] & 0x3FFFu);
            write_record(boxes, gt_boxes, gt_classes, meta, out, b, i, (unsigned)s);
        }
    }
}

extern "C" void kernel_launch(void* const* d_in, const int* in_sizes, int n_in,
                              void* d_out, int out_size) {
    (void)out_size;
    const float* boxes      = (const float*)d_in[0];
    const float* gt_boxes   = (const float*)d_in[1];
    const int*   gt_classes = (const int*)d_in[2];
    for (int k = 0; k < n_in; ++k) {
        if (in_sizes[k] == BB * NBOX * 4) boxes      = (const float*)d_in[k];
        else if (in_sizes[k] == BB * MGT * 4) gt_boxes = (const float*)d_in[k];
        else if (in_sizes[k] == BB * MGT)     gt_classes = (const int*)d_in[k];
    }
    float* out = (float*)d_out;

    dim3 g1(NP / 256, BB);
    roi_match_kernel<<<g1, 256>>>(boxes, gt_boxes);

    size_t smem = (size_t)SORTN * 8 + (size_t)NP * 4 + 1024 * 4
                + (size_t)NSAMP * 8;   // 173056 B
    cudaFuncSetAttribute(roi_sample_kernel,
                         cudaFuncAttributeMaxDynamicSharedMemorySize, (int)smem);
    roi_sample_kernel<<<BB, 1024, smem>>>(boxes, gt_boxes, gt_classes, out);
}

// round 4
// speedup vs baseline: 5.1060x; 5.1060x over previous
#include <cuda_runtime.h>
#include <stdint.h>

#define BB    32
#define NBOX  8192
#define MGT   256
#define NP    8448        // NBOX + MGT
#define NSAMP 512
#define NFG   128
#define NBIN  2048
#define CAP   512

// scratch (device globals -- no allocation allowed)
__device__ unsigned long long g_keys[BB * NP];
__device__ unsigned int       g_meta[BB * NP];

__device__ __forceinline__ uint32_t rotl32(uint32_t x, int d) {
    return (x << d) | (x >> (32 - d));
}

// JAX *partitionable* threefry, key = (0, 42). bits(p) = x0 ^ x1 of
// threefry2x32((0,42), (0, p))
__device__ __forceinline__ uint32_t threefry_bits(uint32_t p) {
    const uint32_t ks0 = 0u, ks1 = 42u, ks2 = 0x1BD11BF0u;  // 0x1BD11BDA ^ 0 ^ 42
    uint32_t x0 = 0u + ks0;
    uint32_t x1 = p + ks1;
#define TF_R(r) { x0 += x1; x1 = rotl32(x1, (r)); x1 ^= x0; }
    TF_R(13) TF_R(15) TF_R(26) TF_R(6)   x0 += ks1; x1 += ks2 + 1u;
    TF_R(17) TF_R(29) TF_R(16) TF_R(24)  x0 += ks2; x1 += ks0 + 2u;
    TF_R(13) TF_R(15) TF_R(26) TF_R(6)   x0 += ks0; x1 += ks1 + 3u;
    TF_R(17) TF_R(29) TF_R(16) TF_R(24)  x0 += ks1; x1 += ks2 + 4u;
    TF_R(13) TF_R(15) TF_R(26) TF_R(6)   x0 += ks2; x1 += ks0 + 5u;
#undef TF_R
    return x0 ^ x1;
}

// ---------------------------------------------------------------------------
// Kernel 1: per-box max-IoU matching + classification + threefry sort key.
// ---------------------------------------------------------------------------
__global__ __launch_bounds__(256)
void roi_match_kernel(const float* __restrict__ boxes,
                      const float* __restrict__ gt_boxes) {
    __shared__ float4 sg[MGT];
    __shared__ float  sga[MGT];

    const int b = blockIdx.y;
    {
        const int j = threadIdx.x;               // 256 threads == MGT
        float4 g = ((const float4*)gt_boxes)[b * MGT + j];
        float mx = fmaxf(fmaxf(g.x, g.y), fmaxf(g.z, g.w));
        float area = (g.z - g.x) * (g.w - g.y);
        if (mx < 0.0f) {                         // invalid gt -> force rejection
            g.x = 1e30f; g.y = 1e30f; g.z = -1e30f; g.w = -1e30f;
            area = 0.0f;
        }
        sg[j] = g; sga[j] = area;
    }
    __syncthreads();

    const int i = blockIdx.x * 256 + threadIdx.x;   // grid exact: i < NP
    float4 bx = (i < NBOX) ? ((const float4*)boxes)[b * NBOX + i]
                           : ((const float4*)gt_boxes)[b * MGT + (i - NBOX)];
    const float ab = (bx.z - bx.x) * (bx.w - bx.y);

    float bi = -1.0f, bu = 1.0f;   // best (inter, union)
    int mi = 0;
#pragma unroll 4
    for (int g = 0; g < MGT; ++g) {
        float4 gb = sg[g];
        float dy = fminf(bx.z, gb.z) - fmaxf(bx.x, gb.x);
        float dx = fminf(bx.w, gb.w) - fmaxf(bx.y, gb.y);
        if (dy > 0.0f && dx > 0.0f) {
            float inter = dy * dx;
            float uni   = (ab + sga[g]) - inter;
            // inter/uni > bi/bu  <=>  inter*bu > bi*uni  (uni, bu > 0)
            if (inter * bu > bi * uni) { bi = inter; bu = uni; mi = g; }
        }
    }
    bool pos = (bi > 0.0f) && (__fdiv_rn(bi, bu) >= 0.5f);

    uint32_t p = (uint32_t)(b * NP + i);
    uint32_t m = threefry_bits(p) >> 9;       // 23-bit mantissa; order(r)==order(m)
    g_keys[b * NP + i] =
        (((unsigned long long)(0x7FFFFFu - m)) << 14) | (unsigned)i;  // asc == r desc, idx asc
    g_meta[b * NP + i] = (unsigned)mi | (pos ? (1u << 16) : 0u);
}

// ---------------------------------------------------------------------------
// Kernel 2: per-image histogram radix-select + 512-sort + gather.
// ---------------------------------------------------------------------------
__device__ __forceinline__ void write_record(
    const float* __restrict__ boxes, const float* __restrict__ gt_boxes,
    const int* __restrict__ gt_classes, const unsigned int* meta,
    float* __restrict__ out, int b, unsigned i, unsigned slot)
{
    float4 roi = (i < NBOX)
        ? ((const float4*)boxes)[b * NBOX + i]
        : ((const float4*)gt_boxes)[b * MGT + (i - NBOX)];
    unsigned mt = meta[i];
    bool pos = (mt >> 16) & 1u;
    int  mi  = (int)(mt & 0xFFFFu);
    float4 gb = make_float4(0.f, 0.f, 0.f, 0.f);
    float cls = 0.0f, gidx = -1.0f;
    if (pos) {
        gb   = ((const float4*)gt_boxes)[b * MGT + mi];
        cls  = (float)gt_classes[b * MGT + mi];
        gidx = (float)mi;
    }
    size_t base = (size_t)(b * NSAMP + slot);
    float* o1 = out + base * 4;                                   // rois
    o1[0] = roi.x; o1[1] = roi.y; o1[2] = roi.z; o1[3] = roi.w;
    float* o2 = out + (size_t)BB * NSAMP * 4 + base * 4;          // matched gt boxes
    o2[0] = gb.x; o2[1] = gb.y; o2[2] = gb.z; o2[3] = gb.w;
    out[(size_t)2 * BB * NSAMP * 4 + base] = cls;                 // classes
    out[(size_t)2 * BB * NSAMP * 4 + (size_t)BB * NSAMP + base] = gidx; // indices
}

__global__ __launch_bounds__(1024)
void roi_sample_kernel(const float* __restrict__ boxes,
                       const float* __restrict__ gt_boxes,
                       const int*   __restrict__ gt_classes,
                       float* __restrict__ out) {
    extern __shared__ unsigned char smem_raw[];
    unsigned long long* keys = (unsigned long long*)smem_raw;    // NP
    unsigned long long* LP   = keys + NP;                        // CAP
    unsigned long long* LN   = LP + CAP;                         // CAP
    unsigned long long* selk = LN + CAP;                         // NSAMP
    unsigned int*       meta = (unsigned int*)(selk + NSAMP);    // NP
    unsigned int*       hP   = meta + NP;                        // NBIN
    unsigned int*       hN   = hP + NBIN;                        // NBIN

    __shared__ unsigned sh_bp, sh_bn, sh_befP, sh_befN;
    __shared__ unsigned cntP, cntN, cntS;
    __shared__ unsigned long long sh_KP, sh_KN;

    const int b = blockIdx.x;
    const int t = threadIdx.x;
    const int T = 1024;

    if (t == 0) {
        cntP = 0; cntN = 0; cntS = 0;
        sh_KP = ~0ull; sh_KN = ~0ull;
    }
    for (int k = t; k < NBIN; k += T) { hP[k] = 0u; hN[k] = 0u; }

    // load keys + meta, build histograms on top-11 key bits (bits 36..26)
    for (int p = t; p < NP; p += T) {
        unsigned long long w = g_keys[b * NP + p];
        unsigned mt = g_meta[b * NP + p];
        keys[p] = w; meta[p] = mt;
    }
    __syncthreads();   // hist zeros visible
    for (int p = t; p < NP; p += T) {
        unsigned long long w = keys[p];
        unsigned bin = (unsigned)(w >> 26);
        if ((meta[(unsigned)(w & 0x3FFFu)] >> 16) & 1u) atomicAdd(&hP[bin], 1u);
        else                                            atomicAdd(&hN[bin], 1u);
    }
    __syncthreads();

    // inclusive scan of both 2048-bin histograms (Hillis-Steele, 2 pos/thread)
    for (int off = 1; off < NBIN; off <<= 1) {
        int i0 = t, i1 = t + T;
        unsigned a0 = 0, a1 = 0, b0 = 0, b1 = 0;
        if (i0 >= off) { a0 = hP[i0 - off]; b0 = hN[i0 - off]; }
        if (i1 >= off) { a1 = hP[i1 - off]; b1 = hN[i1 - off]; }
        __syncthreads();
        hP[i0] += a0; hN[i0] += b0;
        hP[i1] += a1; hN[i1] += b1;
        __syncthreads();
    }

    const unsigned total_pos = hP[NBIN - 1];
    const unsigned n_pos = (total_pos < (unsigned)NFG) ? total_pos : (unsigned)NFG;
    const unsigned quota = (unsigned)NSAMP - n_pos;

    // find boundary bins: first bin where cumulative count reaches the rank
    {
        int i0 = t, i1 = t + T;
        if (total_pos > (unsigned)NFG) {
            unsigned c0 = hP[i0], p0 = i0 ? hP[i0 - 1] : 0u;
            unsigned c1 = hP[i1], p1 = hP[i1 - 1];
            if (c0 >= (unsigned)NFG && p0 < (unsigned)NFG) { sh_bp = (unsigned)i0; sh_befP = p0; }
            if (c1 >= (unsigned)NFG && p1 < (unsigned)NFG) { sh_bp = (unsigned)i1; sh_befP = p1; }
        }
        unsigned c0 = hN[i0], p0 = i0 ? hN[i0 - 1] : 0u;
        unsigned c1 = hN[i1], p1 = hN[i1 - 1];
        if (c0 >= quota && p0 < quota) { sh_bn = (unsigned)i0; sh_befN = p0; }
        if (c1 >= quota && p1 < quota) { sh_bn = (unsigned)i1; sh_befN = p1; }
    }
    __syncthreads();

    // collect boundary-bin items (expected ~4 each)
    const bool needPsel = (total_pos > (unsigned)NFG);
    {
        unsigned bp = needPsel ? sh_bp : 0xFFFFFFFFu;
        unsigned bn = sh_bn;
        for (int p = t; p < NP; p += T) {
            unsigned long long w = keys[p];
            unsigned bin = (unsigned)(w >> 26);
            bool pos = (meta[(unsigned)(w & 0x3FFFu)] >> 16) & 1u;
            if (pos) {
                if (bin == bp) { unsigned j = atomicAdd(&cntP, 1u); if (j < CAP) LP[j] = w; }
            } else {
                if (bin == bn) { unsigned j = atomicAdd(&cntN, 1u); if (j < CAP) LN[j] = w; }
            }
        }
    }
    __syncthreads();

    // exact rank within boundary bins -> cutoff keys (keys are unique)
    {
        unsigned cp = cntP < CAP ? cntP : CAP;
        unsigned cn = cntN < CAP ? cntN : CAP;
        if (needPsel && (unsigned)t < cp) {
            unsigned long long k = LP[t]; unsigned r = 0;
            for (unsigned l = 0; l < cp; ++l) r += (LP[l] < k);
            if (r == ((unsigned)NFG - sh_befP) - 1u) sh_KP = k;
        }
        if ((unsigned)t < cn) {
            unsigned long long k = LN[t]; unsigned r = 0;
            for (unsigned l = 0; l < cn; ++l) r += (LN[l] < k);
            if (r == (quota - sh_befN) - 1u) sh_KN = k;
        }
    }
    __syncthreads();

    // final selection: exactly 512 items; re-key by RNE-rounded score mantissa.
    // score = 2.0f + r rounds r's 23-bit mantissa m to 2^-22 grid:
    //   h = (m>>1) + ((m&1) & ((m>>1)&1)); ties broken by idx asc.
    {
        unsigned long long KP = sh_KP, KN = sh_KN;
        for (int p = t; p < NP; p += T) {
            unsigned long long w = keys[p];
            unsigned i = (unsigned)(w & 0x3FFFu);
            bool pos = (meta[i] >> 16) & 1u;
            bool sel = pos ? (w <= KP) : (w <= KN);
            if (sel) {
                unsigned mm = 0x7FFFFFu - (unsigned)((w >> 14) & 0x7FFFFFu);
                unsigned h  = (mm >> 1) + ((mm & 1u) & ((mm >> 1) & 1u));
                unsigned j  = atomicAdd(&cntS, 1u);
                selk[j] = (((unsigned long long)(0x7FFFFFu - h)) << 14) | i;
            }
        }
    }
    __syncthreads();

    // bitonic sort the 512 selected keys (ascending == score desc, idx asc)
    for (unsigned k = 2; k <= (unsigned)NSAMP; k <<= 1) {
        for (unsigned j = k >> 1; j > 0; j >>= 1) {
            if (t < NSAMP) {
                unsigned p = (unsigned)t, q = p ^ j;
                if (q > p) {
                    unsigned long long a = selk[p], c = selk[q];
                    bool up = ((p & k) == 0);
                    if ((a > c) == up) { selk[p] = c; selk[q] = a; }
                }
            }
            __syncthreads();
        }
    }

    // gather outputs
    if (t < NSAMP) {
        unsigned i = (unsigned)(selk[t] & 0x3FFFu);
        write_record(boxes, gt_boxes, gt_classes, meta, out, b, i, (unsigned)t);
    }
}

extern "C" void kernel_launch(void* const* d_in, const int* in_sizes, int n_in,
                              void* d_out, int out_size) {
    (void)out_size;
    const float* boxes      = (const float*)d_in[0];
    const float* gt_boxes   = (const float*)d_in[1];
    const int*   gt_classes = (const int*)d_in[2];
    for (int k = 0; k < n_in; ++k) {
        if (in_sizes[k] == BB * NBOX * 4) boxes      = (const float*)d_in[k];
        else if (in_sizes[k] == BB * MGT * 4) gt_boxes = (const float*)d_in[k];
        else if (in_sizes[k] == BB * MGT)     gt_classes = (const int*)d_in[k];
    }
    float* out = (float*)d_out;

    dim3 g1(NP / 256, BB);
    roi_match_kernel<<<g1, 256>>>(boxes, gt_boxes);

    size_t smem = (size_t)NP * 8 + 2 * (size_t)CAP * 8 + (size_t)NSAMP * 8
                + (size_t)NP * 4 + 2 * (size_t)NBIN * 4;   // ~130 KB
    cudaFuncSetAttribute(roi_sample_kernel,
                         cudaFuncAttributeMaxDynamicSharedMemorySize, (int)smem);
    roi_sample_kernel<<<BB, 1024, smem>>>(boxes, gt_boxes, gt_classes, out);
}